// round 10
// baseline (speedup 1.0000x reference)
#include <cuda_runtime.h>
#include <cuda_bf16.h>

// ---------------- problem constants ----------------
#define Bn   1024
#define Sn   50
#define Hn   128
#define Kn   4
#define Vn   100000
#define KSn  200            // K*S
#define VP   100096         // V padded to 782*128
#define NVT  782            // v tiles of 128
#define NCHUNK 74           // v-tile chunks (74 x 2 m-halves = 148 CTAs)
#define BKH  (Bn*Kn*Hn)     // 524288

typedef unsigned long long ull;

// ---------------- scratch (no allocations allowed) ----------------
__device__ float g_h[Bn*Sn*Hn];        // 26.2 MB  h = seq_emb @ W^T
__device__ float g_cw[KSn*Bn];         // routing logits, [ks][b]
__device__ float g_colsum[KSn];
__device__ float g_ie4[Bn*32];         // item_e (zeroed row0) summed in groups of 4
__device__ float g_ie4r[Bn*32];        // raw emb row summed in groups of 4
__device__ float g_tgt[Bn];
__device__ float g_partial[80*Bn];     // exp-sum partials [chunk][b]
__device__ float g_ue_scratch[BKH];
__device__ float g_loss_scratch[4];
// bf16 operands, plain row-major [row][128] (256B rows)
__device__ __align__(256) unsigned g_embbf_u[VP*64];    // 25.6 MB (zero-padded rows)
__device__ __align__(256) unsigned g_bestbf_u[Bn*64];   // 256 KB (pre-scaled by log2e)
__device__ __align__(256) unsigned g_wbf_hi[Hn*64];     // W split hi [n][k]
__device__ __align__(256) unsigned g_wbf_lo[Hn*64];     // W split lo
__device__ unsigned g_kd_done;

// ---------------- helpers ----------------
__device__ __forceinline__ float ex2f(float x) {
    float r; asm("ex2.approx.f32 %0, %1;" : "=f"(r) : "f"(x)); return r;
}
__device__ __forceinline__ unsigned smem_u32(const void* p) {
    unsigned a;
    asm("{ .reg .u64 t; cvta.to.shared.u64 t, %1; cvt.u32.u64 %0, t; }" : "=r"(a) : "l"(p));
    return a;
}
__device__ __forceinline__ void cp16(unsigned dst, const void* src) {
    asm volatile("cp.async.cg.shared.global [%0], [%1], 16;" :: "r"(dst), "l"(src) : "memory");
}
#define CP_COMMIT()  asm volatile("cp.async.commit_group;" ::: "memory")
#define CP_WAIT(N)   asm volatile("cp.async.wait_group %0;" :: "n"(N) : "memory")

__device__ __forceinline__ void ldsm_x4(unsigned& r0, unsigned& r1, unsigned& r2, unsigned& r3,
                                        unsigned addr) {
    asm volatile("ldmatrix.sync.aligned.m8n8.x4.shared.b16 {%0,%1,%2,%3}, [%4];"
        : "=r"(r0), "=r"(r1), "=r"(r2), "=r"(r3) : "r"(addr));
}
__device__ __forceinline__ void mma16816(float* c, const unsigned* a, unsigned b0, unsigned b1) {
    asm volatile("mma.sync.aligned.m16n8k16.row.col.f32.bf16.bf16.f32 "
        "{%0,%1,%2,%3}, {%4,%5,%6,%7}, {%8,%9}, {%0,%1,%2,%3};"
        : "+f"(c[0]), "+f"(c[1]), "+f"(c[2]), "+f"(c[3])
        : "r"(a[0]), "r"(a[1]), "r"(a[2]), "r"(a[3]), "r"(b0), "r"(b1));
}
__device__ __forceinline__ unsigned pack_bf16(float x, float y) {
    unsigned lo = (unsigned)__bfloat16_as_ushort(__float2bfloat16(x));
    unsigned hi = (unsigned)__bfloat16_as_ushort(__float2bfloat16(y));
    return lo | (hi << 16);
}

// ---------------- small prep kernels ----------------
// emb fp32 -> bf16 row-major [v][128] (pad rows v>=Vn exact zeros)
__global__ __launch_bounds__(256) void k_conv_emb(const float* __restrict__ emb) {
    int idx = blockIdx.x * 256 + threadIdx.x;      // VP*64 threads
    int v = idx >> 6, u = idx & 63;
    float2 e = make_float2(0.f, 0.f);
    if (v < Vn) e = *(const float2*)(emb + (ull)v*Hn + u*2);
    g_embbf_u[idx] = pack_bf16(e.x, e.y);
}

// W -> bf16 hi/lo split (no transpose: B operand rows are n, K-contiguous)
__global__ __launch_bounds__(256) void k_conv_w(const float* __restrict__ W) {
    int idx = blockIdx.x * 256 + threadIdx.x;      // 128*64 threads
    float2 e = *(const float2*)(W + idx*2);
    __nv_bfloat16 hx = __float2bfloat16(e.x), hy = __float2bfloat16(e.y);
    float lx = e.x - __bfloat162float(hx), ly = e.y - __bfloat162float(hy);
    g_wbf_hi[idx] = ((unsigned)__bfloat16_as_ushort(hx)) | (((unsigned)__bfloat16_as_ushort(hy)) << 16);
    g_wbf_lo[idx] = pack_bf16(lx, ly);
}

__global__ void k_ie4(const int* __restrict__ item, const float* __restrict__ emb) {
    int b = blockIdx.x, c = threadIdx.x;
    int idx = item[b];
    float4 v = ((const float4*)emb)[idx*32 + c];
    float s = v.x + v.y + v.z + v.w;
    g_ie4r[b*32 + c] = s;                          // raw (for target score)
    g_ie4[b*32 + c] = (idx != 0) ? s : 0.f;        // emb_lookup zeroes row 0
}

// cw0 [b][ks] -> g_cw [ks][b], tiled transpose. grid (32,7), block (32,8)
__global__ void k_init_cw(const float* __restrict__ cw0) {
    __shared__ float t[32][33];
    int b0 = blockIdx.x*32, k0 = blockIdx.y*32;
    int tx = threadIdx.x, ty = threadIdx.y;
    #pragma unroll
    for (int r = ty; r < 32; r += 8)
        if (k0 + tx < KSn) t[r][tx] = cw0[(size_t)(b0+r)*KSn + k0 + tx];
    __syncthreads();
    #pragma unroll
    for (int r = ty; r < 32; r += 8)
        if (k0 + r < KSn) g_cw[(size_t)(k0+r)*Bn + b0 + tx] = t[tx][r];
}

// ---------------- h = seq_emb @ W^T via split-bf16 HMMA (round-7 version, measured 35us) ----------------
#define KH_SMEM (4*32768)
__global__ __launch_bounds__(256, 1) void k_h_mma(const int* __restrict__ item_seq,
                                                  const float* __restrict__ emb) {
    extern __shared__ char hsm_raw[];
    int tid = threadIdx.x, wid = tid >> 5, lane = tid & 31;
    int blk = blockIdx.x;

    unsigned aH = smem_u32(hsm_raw);
    unsigned aL = aH + 32768u;
    unsigned wH = aH + 65536u;
    unsigned wL = aH + 98304u;

    {
        int row = tid >> 1, c0 = (tid & 1) * 8;
        #pragma unroll
        for (int j = 0; j < 8; j++) {
            int c16 = c0 + j;
            cp16(wH + row*256 + ((c16 ^ (row & 7)) << 4), (const char*)g_wbf_hi + row*256 + c16*16);
            cp16(wL + row*256 + ((c16 ^ (row & 7)) << 4), (const char*)g_wbf_lo + row*256 + c16*16);
        }
    }
    CP_COMMIT();

    {
        int row = tid >> 1, half = tid & 1;
        int idx = item_seq[blk*128 + row];
        const float* src = emb + (size_t)idx*Hn + half*64;
        bool z = (idx == 0);
        #pragma unroll
        for (int j = 0; j < 8; j++) {
            int c16 = half*8 + j;
            float4 f0 = z ? make_float4(0,0,0,0) : *(const float4*)(src + j*8);
            float4 f1 = z ? make_float4(0,0,0,0) : *(const float4*)(src + j*8 + 4);
            uint4 hiq, loq;
            {
                __nv_bfloat16 h0=__float2bfloat16(f0.x), h1=__float2bfloat16(f0.y);
                __nv_bfloat16 h2=__float2bfloat16(f0.z), h3=__float2bfloat16(f0.w);
                __nv_bfloat16 h4=__float2bfloat16(f1.x), h5=__float2bfloat16(f1.y);
                __nv_bfloat16 h6=__float2bfloat16(f1.z), h7=__float2bfloat16(f1.w);
                hiq.x = ((unsigned)__bfloat16_as_ushort(h0)) | (((unsigned)__bfloat16_as_ushort(h1))<<16);
                hiq.y = ((unsigned)__bfloat16_as_ushort(h2)) | (((unsigned)__bfloat16_as_ushort(h3))<<16);
                hiq.z = ((unsigned)__bfloat16_as_ushort(h4)) | (((unsigned)__bfloat16_as_ushort(h5))<<16);
                hiq.w = ((unsigned)__bfloat16_as_ushort(h6)) | (((unsigned)__bfloat16_as_ushort(h7))<<16);
                loq.x = pack_bf16(f0.x-__bfloat162float(h0), f0.y-__bfloat162float(h1));
                loq.y = pack_bf16(f0.z-__bfloat162float(h2), f0.w-__bfloat162float(h3));
                loq.z = pack_bf16(f1.x-__bfloat162float(h4), f1.y-__bfloat162float(h5));
                loq.w = pack_bf16(f1.z-__bfloat162float(h6), f1.w-__bfloat162float(h7));
            }
            unsigned off = row*256 + ((c16 ^ (row & 7)) << 4);
            asm volatile("st.shared.v4.b32 [%0], {%1,%2,%3,%4};" :: "r"(aH+off),
                         "r"(hiq.x), "r"(hiq.y), "r"(hiq.z), "r"(hiq.w) : "memory");
            asm volatile("st.shared.v4.b32 [%0], {%1,%2,%3,%4};" :: "r"(aL+off),
                         "r"(loq.x), "r"(loq.y), "r"(loq.z), "r"(loq.w) : "memory");
        }
    }
    CP_WAIT(0);
    __syncthreads();

    int rA = wid*16 + (lane & 7) + ((lane >> 3) & 1) * 8;
    int kcA = lane >> 4;
    unsigned ah[8][4], al[8][4];
    #pragma unroll
    for (int k = 0; k < 8; k++) {
        int c16 = k*2 + kcA;
        unsigned off = rA*256 + ((c16 ^ (rA & 7)) << 4);
        ldsm_x4(ah[k][0], ah[k][1], ah[k][2], ah[k][3], aH + off);
        ldsm_x4(al[k][0], al[k][1], al[k][2], al[k][3], aL + off);
    }

    int rBl = ((lane >> 4) & 1) * 8 + (lane & 7);
    int khB = (lane >> 3) & 1;
    #pragma unroll 1
    for (int np = 0; np < 8; np++) {
        int rB = np*16 + rBl;
        float cc[8];
        #pragma unroll
        for (int j = 0; j < 8; j++) cc[j] = 0.f;
        #pragma unroll
        for (int k = 0; k < 8; k++) {
            int c16 = k*2 + khB;
            unsigned off = rB*256 + ((c16 ^ (rB & 7)) << 4);
            unsigned bh0, bh1, bh2, bh3, bl0, bl1, bl2, bl3;
            ldsm_x4(bh0, bh1, bh2, bh3, wH + off);
            ldsm_x4(bl0, bl1, bl2, bl3, wL + off);
            mma16816(cc,     ah[k], bh0, bh1);
            mma16816(cc + 4, ah[k], bh2, bh3);
            mma16816(cc,     ah[k], bl0, bl1);
            mma16816(cc + 4, ah[k], bl2, bl3);
            mma16816(cc,     al[k], bh0, bh1);
            mma16816(cc + 4, al[k], bh2, bh3);
        }
        int mrow = blk*128 + wid*16 + (lane >> 2);
        int col  = np*16 + (lane & 3)*2;
        *(float2*)&g_h[(size_t)mrow*Hn + col]         = make_float2(cc[0], cc[1]);
        *(float2*)&g_h[(size_t)(mrow+8)*Hn + col]     = make_float2(cc[2], cc[3]);
        *(float2*)&g_h[(size_t)mrow*Hn + col + 8]     = make_float2(cc[4], cc[5]);
        *(float2*)&g_h[(size_t)(mrow+8)*Hn + col + 8] = make_float2(cc[6], cc[7]);
    }
}

// ---------------- routing: column exp-sum (softmax over batch axis) ----------------
__global__ __launch_bounds__(256) void k_r1() {
    __shared__ float red[256];
    int ks = blockIdx.x, tid = threadIdx.x;
    float sm = 0.f;
    for (int b = tid; b < Bn; b += 256) sm += __expf(g_cw[ks*Bn + b]);
    red[tid] = sm; __syncthreads();
    for (int s = 128; s > 0; s >>= 1) { if (tid < s) red[tid] += red[tid+s]; __syncthreads(); }
    if (tid == 0) g_colsum[ks] = red[0];
}

// ---------------- routing: per-batch capsule update ----------------
template<bool FINAL>
__global__ __launch_bounds__(128) void k_r2(const float* __restrict__ mask,
                                            float* __restrict__ ue_out) {
    __shared__ float hsm[Sn*Hn];
    __shared__ float swsm[KSn];
    __shared__ float capsm[128];
    __shared__ float cossm[4], cosrm[4];
    __shared__ int ksel;
    int b = blockIdx.x, tid = threadIdx.x;

    const float4* hp = (const float4*)(g_h + (size_t)b*Sn*Hn);
    float4* h4 = (float4*)hsm;
    for (int i = tid; i < Sn*Hn/4; i += 128) h4[i] = hp[i];
    for (int t = tid; t < KSn; t += 128) {
        int s = t % Sn;
        float cwv = g_cw[(size_t)t*Bn + b];
        float m = mask[b*Sn + s];
        swsm[t] = (m != 0.f) ? __expf(cwv) / g_colsum[t] : 0.f;
    }
    __syncthreads();

    int k = tid >> 5, c = tid & 31;
    float g = 0.f;
    #pragma unroll
    for (int s = 0; s < Sn; s++) g += swsm[k*Sn + s] * hsm[s*Hn + k*32 + c];

    float n = g*g;
    #pragma unroll
    for (int o = 16; o; o >>= 1) n += __shfl_xor_sync(0xffffffffu, n, o);
    n *= 4.f;
    float sc = n / (1.f + n) / sqrtf(n + 1e-9f);
    float cap = sc * g;

    capsm[tid] = cap;
    if (FINAL) {
        float cz = cap * g_ie4[b*32 + c];
        float cr = cap * g_ie4r[b*32 + c];
        #pragma unroll
        for (int o = 16; o; o >>= 1) {
            cz += __shfl_xor_sync(0xffffffffu, cz, o);
            cr += __shfl_xor_sync(0xffffffffu, cr, o);
        }
        if (c == 0) { cossm[k] = cz; cosrm[k] = cr; }
    }
    __syncthreads();

    if (!FINAL) {
        // delta[k,s] = 4 * sum_c cap[k,c]*h[s,k*32+c]
        #pragma unroll
        for (int pass = 0; pass < 2; pass++) {
            int s = c + pass*32;
            if (s < Sn) {
                float d = 0.f;
                #pragma unroll
                for (int i = 0; i < 32; i++) {
                    int cc2 = (c + i) & 31;
                    d += capsm[k*32 + cc2] * hsm[s*Hn + k*32 + cc2];
                }
                g_cw[(size_t)(k*Sn + s)*Bn + b] += 4.f * d;
            }
        }
    } else {
        if (tid == 0) {
            float bst = -3.4e38f; int kb = 0;
            #pragma unroll
            for (int kk = 0; kk < 4; kk++) if (cossm[kk] > bst) { bst = cossm[kk]; kb = kk; }
            ksel = kb;
            g_tgt[b] = cosrm[kb];         // target score uses RAW emb row
        }
        __syncthreads();
        for (int t = tid; t < 512; t += 128) {
            int kk = t >> 7, j = t & 127;
            ue_out[b*512 + t] = capsm[kk*32 + (j >> 2)];
        }
        if (tid < 64) {
            const float L2E = 1.4426950408889634f;
            float x = capsm[ksel*32 + ((2*tid) >> 2)]     * L2E;
            float y = capsm[ksel*32 + ((2*tid + 1) >> 2)] * L2E;
            g_bestbf_u[b*64 + tid] = pack_bf16(x, y);
        }
    }
}

// ---------------- scores GEMM via HMMA + fused exp2 row-sum + fused loss ----------------
#define KD_SMEM (6*32768)
__device__ __forceinline__ void load_tile(unsigned sbase, const char* gsrc, int tid) {
    int row = tid >> 1;
    int c0  = (tid & 1) * 8;
    const char* g = gsrc + row * 256;
    unsigned s = sbase + row * 256;
    #pragma unroll
    for (int j = 0; j < 8; j++) {
        int c16 = c0 + j;
        cp16(s + ((c16 ^ (row & 7)) << 4), g + c16 * 16);
    }
}

__global__ __launch_bounds__(256, 1) void k_d_mma(float* __restrict__ loss_out) {
    extern __shared__ char dsm[];
    int tid = threadIdx.x, wid = tid >> 5, lane = tid & 31;
    int mhalf = blockIdx.y, c = blockIdx.x;
    int t0  = c*10 + min(c, 42);          // 42 chunks of 11 tiles, 32 of 10
    int cnt = 10 + (c < 42 ? 1 : 0);

    unsigned aS = smem_u32(dsm);          // 4 A tiles: 128KB
    unsigned bS[2] = { aS + 131072u, aS + 163840u };

    const char* aG = (const char*)g_bestbf_u + (size_t)mhalf * 131072;
    #pragma unroll
    for (int f = 0; f < 4; f++)
        load_tile(aS + f*32768u, aG + f*32768, tid);
    load_tile(bS[0], (const char*)g_embbf_u + (size_t)t0 * 32768, tid);
    CP_COMMIT();

    int rloc = (lane & 7) + ((lane >> 3) & 1) * 8;
    int kcA = lane >> 4;
    int rBl = ((lane >> 4) & 1) * 8 + (lane & 7);
    int khB = (lane >> 3) & 1;

    unsigned a[4][8][4];
    float acc[8];
    #pragma unroll
    for (int j = 0; j < 8; j++) acc[j] = 0.f;

    #pragma unroll 1
    for (int t = 0; t < cnt; t++) {
        if (t + 1 < cnt) {
            load_tile(bS[(t + 1) & 1], (const char*)g_embbf_u + (size_t)(t0 + t + 1) * 32768, tid);
            CP_COMMIT();
            CP_WAIT(1);
        } else {
            CP_WAIT(0);
        }
        __syncthreads();

        if (t == 0) {
            #pragma unroll
            for (int f = 0; f < 4; f++) {
                int r = wid*64 + f*16 + rloc;
                #pragma unroll
                for (int k = 0; k < 8; k++) {
                    int c16 = k*2 + kcA;
                    ldsm_x4(a[f][k][0], a[f][k][1], a[f][k][2], a[f][k][3],
                            aS + r*256 + ((c16 ^ (r & 7)) << 4));
                }
            }
        }

        unsigned bb = bS[t & 1];
        #pragma unroll 1
        for (int np = 0; np < 8; np++) {
            int rB = np*16 + rBl;
            unsigned baddr0 = bb + rB*256;
            float cc[32];
            #pragma unroll
            for (int j = 0; j < 32; j++) cc[j] = 0.f;
            #pragma unroll
            for (int k = 0; k < 8; k++) {
                int c16 = k*2 + khB;
                unsigned b0, b1, b2, b3;
                ldsm_x4(b0, b1, b2, b3, baddr0 + ((c16 ^ (rB & 7)) << 4));
                #pragma unroll
                for (int f = 0; f < 4; f++) {
                    mma16816(cc + f*8,     a[f][k], b0, b1);
                    mma16816(cc + f*8 + 4, a[f][k], b2, b3);
                }
            }
            #pragma unroll
            for (int f = 0; f < 4; f++) {
                acc[f*2]   += ex2f(cc[f*8+0]) + ex2f(cc[f*8+1]) + ex2f(cc[f*8+4]) + ex2f(cc[f*8+5]);
                acc[f*2+1] += ex2f(cc[f*8+2]) + ex2f(cc[f*8+3]) + ex2f(cc[f*8+6]) + ex2f(cc[f*8+7]);
            }
        }
        __syncthreads();
    }

    #pragma unroll
    for (int j = 0; j < 8; j++) {
        acc[j] += __shfl_xor_sync(0xffffffffu, acc[j], 1);
        acc[j] += __shfl_xor_sync(0xffffffffu, acc[j], 2);
    }
    if ((lane & 3) == 0) {
        int r0 = mhalf*512 + wid*64 + (lane >> 2);
        #pragma unroll
        for (int f = 0; f < 4; f++) {
            g_partial[c*Bn + r0 + f*16]     = acc[f*2];
            g_partial[c*Bn + r0 + f*16 + 8] = acc[f*2+1];
        }
    }

    // ---- fused loss: the 148th CTA to finish reduces everything (fixed order) ----
    __syncthreads();
    __shared__ unsigned lastf;
    if (tid == 0) {
        __threadfence();
        lastf = (atomicAdd(&g_kd_done, 1u) == (unsigned)(NCHUNK*2 - 1)) ? 1u : 0u;
    }
    __syncthreads();
    if (lastf) {
        __threadfence();
        float mine = 0.f;
        #pragma unroll
        for (int rr = 0; rr < 4; rr++) {
            int r = tid + rr*256;
            float a2 = -96.0f;   // remove exp(0)=1 from the 96 zero-padded v columns
            #pragma unroll 1
            for (int cc2 = 0; cc2 < NCHUNK; cc2++) a2 += __ldcg(&g_partial[cc2*Bn + r]);
            mine += g_tgt[r] - logf(a2);
        }
        float* red = (float*)dsm;
        red[tid] = mine;
        __syncthreads();
        for (int o = 128; o; o >>= 1) { if (tid < o) red[tid] += red[tid+o]; __syncthreads(); }
        if (tid == 0) {
            loss_out[0] = -red[0] / (float)Bn;
            atomicExch(&g_kd_done, 0u);   // replay-safe reset
        }
    }
}

// ---------------- host launcher ----------------
extern "C" void kernel_launch(void* const* d_in, const int* in_sizes, int n_in,
                              void* d_out, int out_size) {
    const int*   item_seq = (const int*)  d_in[0];
    const float* mask     = (const float*)d_in[1];
    const int*   item     = (const int*)  d_in[2];
    const float* emb      = (const float*)d_in[3];
    const float* W        = (const float*)d_in[4];
    const float* cw0      = (const float*)d_in[5];
    float* out = (float*)d_out;

    float *ue_ptr, *loss_ptr;
    if (out_size >= BKH + 1)      { ue_ptr = out;          loss_ptr = out + BKH; }
    else if (out_size == BKH)     { ue_ptr = out;          loss_ptr = g_loss_scratch; }
    else                          { ue_ptr = g_ue_scratch; loss_ptr = out + (out_size > 0 ? out_size - 1 : 0); }

    cudaFuncSetAttribute(k_h_mma, cudaFuncAttributeMaxDynamicSharedMemorySize, KH_SMEM);
    cudaFuncSetAttribute(k_d_mma, cudaFuncAttributeMaxDynamicSharedMemorySize, KD_SMEM);

    // side stream: cw transpose + r1_0 + ie4 + emb bf16 conversion,
    // concurrent with conv_w -> k_h on the main stream.
    cudaStream_t s2; cudaEvent_t evF, evR, evE;
    cudaStreamCreateWithFlags(&s2, cudaStreamNonBlocking);
    cudaEventCreateWithFlags(&evF, cudaEventDisableTiming);
    cudaEventCreateWithFlags(&evR, cudaEventDisableTiming);
    cudaEventCreateWithFlags(&evE, cudaEventDisableTiming);
    cudaEventRecord(evF, 0);
    cudaStreamWaitEvent(s2, evF, 0);
    k_init_cw<<<dim3(32, 7), dim3(32, 8), 0, s2>>>(cw0);
    k_r1<<<KSn, 256, 0, s2>>>();                 // colsum for routing iter 0
    k_ie4<<<Bn, 32, 0, s2>>>(item, emb);
    cudaEventRecord(evR, s2);
    k_conv_emb<<<(VP*64)/256, 256, 0, s2>>>(emb);
    cudaEventRecord(evE, s2);

    // main chain
    k_conv_w<<<(Hn*64)/256, 256>>>(W);
    k_h_mma<<<(Bn*Sn)/128, 256, KH_SMEM>>>(item_seq, emb);

    cudaStreamWaitEvent(0, evR, 0);              // routing prologue ready
    k_r2<false><<<Bn, 128>>>(mask, ue_ptr);
    k_r1<<<KSn, 256>>>();
    k_r2<false><<<Bn, 128>>>(mask, ue_ptr);
    k_r1<<<KSn, 256>>>();
    k_r2<true ><<<Bn, 128>>>(mask, ue_ptr);

    cudaStreamWaitEvent(0, evE, 0);              // emb bf16 ready
    k_d_mma<<<dim3(NCHUNK, 2), 256, KD_SMEM>>>(loss_ptr);
}

// round 11
// speedup vs baseline: 1.2990x; 1.2990x over previous
#include <cuda_runtime.h>
#include <cuda_bf16.h>

// ---------------- problem constants ----------------
#define Bn   1024
#define Sn   50
#define Hn   128
#define Kn   4
#define Vn   100000
#define KSn  200            // K*S
#define VP   100096         // V padded to 782*128
#define NVT  782            // v tiles of 128
#define NCHUNK 74           // v-tile chunks (74 x 2 m-halves = 148 CTAs)
#define BKH  (Bn*Kn*Hn)     // 524288

typedef unsigned long long ull;

// ---------------- scratch (no allocations allowed) ----------------
__device__ float g_h[Bn*Sn*Hn];        // 26.2 MB  h = seq_emb @ W^T
__device__ float g_cw[KSn*Bn];         // routing logits, [ks][b]
__device__ float g_colsum[KSn];
__device__ float g_ie4[Bn*32];         // item_e (zeroed row0) summed in groups of 4
__device__ float g_ie4r[Bn*32];        // raw emb row summed in groups of 4
__device__ float g_tgt[Bn];
__device__ float g_partial[80*Bn];     // exp-sum partials [chunk][b]
__device__ float g_ue_scratch[BKH];
__device__ float g_loss_scratch[4];
// bf16 operands, plain row-major [row][128] (256B rows)
__device__ __align__(256) unsigned g_embbf_u[VP*64];    // 25.6 MB (zero-padded rows)
__device__ __align__(256) unsigned g_bestbf_u[Bn*64];   // 256 KB (pre-scaled by log2e)
__device__ __align__(256) unsigned g_wbf_hi[Hn*64];     // W split hi [n][k]
__device__ __align__(256) unsigned g_wbf_lo[Hn*64];     // W split lo

// ---------------- helpers ----------------
__device__ __forceinline__ float ex2f(float x) {
    float r; asm("ex2.approx.f32 %0, %1;" : "=f"(r) : "f"(x)); return r;
}
__device__ __forceinline__ unsigned smem_u32(const void* p) {
    unsigned a;
    asm("{ .reg .u64 t; cvta.to.shared.u64 t, %1; cvt.u32.u64 %0, t; }" : "=r"(a) : "l"(p));
    return a;
}
__device__ __forceinline__ void cp16(unsigned dst, const void* src) {
    asm volatile("cp.async.cg.shared.global [%0], [%1], 16;" :: "r"(dst), "l"(src) : "memory");
}
#define CP_COMMIT()  asm volatile("cp.async.commit_group;" ::: "memory")
#define CP_WAIT(N)   asm volatile("cp.async.wait_group %0;" :: "n"(N) : "memory")

__device__ __forceinline__ void ldsm_x4(unsigned& r0, unsigned& r1, unsigned& r2, unsigned& r3,
                                        unsigned addr) {
    asm volatile("ldmatrix.sync.aligned.m8n8.x4.shared.b16 {%0,%1,%2,%3}, [%4];"
        : "=r"(r0), "=r"(r1), "=r"(r2), "=r"(r3) : "r"(addr));
}
__device__ __forceinline__ void mma16816(float* c, const unsigned* a, unsigned b0, unsigned b1) {
    asm volatile("mma.sync.aligned.m16n8k16.row.col.f32.bf16.bf16.f32 "
        "{%0,%1,%2,%3}, {%4,%5,%6,%7}, {%8,%9}, {%0,%1,%2,%3};"
        : "+f"(c[0]), "+f"(c[1]), "+f"(c[2]), "+f"(c[3])
        : "r"(a[0]), "r"(a[1]), "r"(a[2]), "r"(a[3]), "r"(b0), "r"(b1));
}
__device__ __forceinline__ unsigned pack_bf16(float x, float y) {
    unsigned lo = (unsigned)__bfloat16_as_ushort(__float2bfloat16(x));
    unsigned hi = (unsigned)__bfloat16_as_ushort(__float2bfloat16(y));
    return lo | (hi << 16);
}

// ---------------- small prep kernels ----------------
// emb fp32 -> bf16 row-major [v][128] (pad rows v>=Vn exact zeros)
__global__ __launch_bounds__(256) void k_conv_emb(const float* __restrict__ emb) {
    int idx = blockIdx.x * 256 + threadIdx.x;      // VP*64 threads
    int v = idx >> 6, u = idx & 63;
    float2 e = make_float2(0.f, 0.f);
    if (v < Vn) e = *(const float2*)(emb + (ull)v*Hn + u*2);
    g_embbf_u[idx] = pack_bf16(e.x, e.y);
}

// W -> bf16 hi/lo split (no transpose: B operand rows are n, K-contiguous)
__global__ __launch_bounds__(256) void k_conv_w(const float* __restrict__ W) {
    int idx = blockIdx.x * 256 + threadIdx.x;      // 128*64 threads
    float2 e = *(const float2*)(W + idx*2);
    __nv_bfloat16 hx = __float2bfloat16(e.x), hy = __float2bfloat16(e.y);
    float lx = e.x - __bfloat162float(hx), ly = e.y - __bfloat162float(hy);
    g_wbf_hi[idx] = ((unsigned)__bfloat16_as_ushort(hx)) | (((unsigned)__bfloat16_as_ushort(hy)) << 16);
    g_wbf_lo[idx] = pack_bf16(lx, ly);
}

__global__ void k_ie4(const int* __restrict__ item, const float* __restrict__ emb) {
    int b = blockIdx.x, c = threadIdx.x;
    int idx = item[b];
    float4 v = ((const float4*)emb)[idx*32 + c];
    float s = v.x + v.y + v.z + v.w;
    g_ie4r[b*32 + c] = s;                          // raw (for target score)
    g_ie4[b*32 + c] = (idx != 0) ? s : 0.f;        // emb_lookup zeroes row 0
}

__global__ void k_init_cw(const float* __restrict__ cw0) {
    int ks = blockIdx.x;
    for (int b = threadIdx.x; b < Bn; b += 256)
        g_cw[ks*Bn + b] = cw0[b*KSn + ks];
}

// ---------------- h = seq_emb @ W^T via split-bf16 HMMA ----------------
#define KH_SMEM (4*32768)
__global__ __launch_bounds__(256, 1) void k_h_mma(const int* __restrict__ item_seq,
                                                  const float* __restrict__ emb) {
    extern __shared__ char hsm_raw[];
    int tid = threadIdx.x, wid = tid >> 5, lane = tid & 31;
    int blk = blockIdx.x;

    unsigned aH = smem_u32(hsm_raw);
    unsigned aL = aH + 32768u;
    unsigned wH = aH + 65536u;
    unsigned wL = aH + 98304u;

    {
        int row = tid >> 1, c0 = (tid & 1) * 8;
        #pragma unroll
        for (int j = 0; j < 8; j++) {
            int c16 = c0 + j;
            cp16(wH + row*256 + ((c16 ^ (row & 7)) << 4), (const char*)g_wbf_hi + row*256 + c16*16);
            cp16(wL + row*256 + ((c16 ^ (row & 7)) << 4), (const char*)g_wbf_lo + row*256 + c16*16);
        }
    }
    CP_COMMIT();

    {
        int row = tid >> 1, half = tid & 1;
        int idx = item_seq[blk*128 + row];
        const float* src = emb + (size_t)idx*Hn + half*64;
        bool z = (idx == 0);
        #pragma unroll
        for (int j = 0; j < 8; j++) {
            int c16 = half*8 + j;
            float4 f0 = z ? make_float4(0,0,0,0) : *(const float4*)(src + j*8);
            float4 f1 = z ? make_float4(0,0,0,0) : *(const float4*)(src + j*8 + 4);
            uint4 hiq, loq;
            {
                __nv_bfloat16 h0=__float2bfloat16(f0.x), h1=__float2bfloat16(f0.y);
                __nv_bfloat16 h2=__float2bfloat16(f0.z), h3=__float2bfloat16(f0.w);
                __nv_bfloat16 h4=__float2bfloat16(f1.x), h5=__float2bfloat16(f1.y);
                __nv_bfloat16 h6=__float2bfloat16(f1.z), h7=__float2bfloat16(f1.w);
                hiq.x = ((unsigned)__bfloat16_as_ushort(h0)) | (((unsigned)__bfloat16_as_ushort(h1))<<16);
                hiq.y = ((unsigned)__bfloat16_as_ushort(h2)) | (((unsigned)__bfloat16_as_ushort(h3))<<16);
                hiq.z = ((unsigned)__bfloat16_as_ushort(h4)) | (((unsigned)__bfloat16_as_ushort(h5))<<16);
                hiq.w = ((unsigned)__bfloat16_as_ushort(h6)) | (((unsigned)__bfloat16_as_ushort(h7))<<16);
                loq.x = pack_bf16(f0.x-__bfloat162float(h0), f0.y-__bfloat162float(h1));
                loq.y = pack_bf16(f0.z-__bfloat162float(h2), f0.w-__bfloat162float(h3));
                loq.z = pack_bf16(f1.x-__bfloat162float(h4), f1.y-__bfloat162float(h5));
                loq.w = pack_bf16(f1.z-__bfloat162float(h6), f1.w-__bfloat162float(h7));
            }
            unsigned off = row*256 + ((c16 ^ (row & 7)) << 4);
            asm volatile("st.shared.v4.b32 [%0], {%1,%2,%3,%4};" :: "r"(aH+off),
                         "r"(hiq.x), "r"(hiq.y), "r"(hiq.z), "r"(hiq.w) : "memory");
            asm volatile("st.shared.v4.b32 [%0], {%1,%2,%3,%4};" :: "r"(aL+off),
                         "r"(loq.x), "r"(loq.y), "r"(loq.z), "r"(loq.w) : "memory");
        }
    }
    CP_WAIT(0);
    __syncthreads();

    int rA = wid*16 + (lane & 7) + ((lane >> 3) & 1) * 8;
    int kcA = lane >> 4;
    unsigned ah[8][4], al[8][4];
    #pragma unroll
    for (int k = 0; k < 8; k++) {
        int c16 = k*2 + kcA;
        unsigned off = rA*256 + ((c16 ^ (rA & 7)) << 4);
        ldsm_x4(ah[k][0], ah[k][1], ah[k][2], ah[k][3], aH + off);
        ldsm_x4(al[k][0], al[k][1], al[k][2], al[k][3], aL + off);
    }

    int rBl = ((lane >> 4) & 1) * 8 + (lane & 7);
    int khB = (lane >> 3) & 1;
    #pragma unroll 1
    for (int np = 0; np < 8; np++) {
        int rB = np*16 + rBl;
        float cc[8];
        #pragma unroll
        for (int j = 0; j < 8; j++) cc[j] = 0.f;
        #pragma unroll
        for (int k = 0; k < 8; k++) {
            int c16 = k*2 + khB;
            unsigned off = rB*256 + ((c16 ^ (rB & 7)) << 4);
            unsigned bh0, bh1, bh2, bh3, bl0, bl1, bl2, bl3;
            ldsm_x4(bh0, bh1, bh2, bh3, wH + off);
            ldsm_x4(bl0, bl1, bl2, bl3, wL + off);
            mma16816(cc,     ah[k], bh0, bh1);
            mma16816(cc + 4, ah[k], bh2, bh3);
            mma16816(cc,     ah[k], bl0, bl1);
            mma16816(cc + 4, ah[k], bl2, bl3);
            mma16816(cc,     al[k], bh0, bh1);
            mma16816(cc + 4, al[k], bh2, bh3);
        }
        int mrow = blk*128 + wid*16 + (lane >> 2);
        int col  = np*16 + (lane & 3)*2;
        *(float2*)&g_h[(size_t)mrow*Hn + col]         = make_float2(cc[0], cc[1]);
        *(float2*)&g_h[(size_t)(mrow+8)*Hn + col]     = make_float2(cc[2], cc[3]);
        *(float2*)&g_h[(size_t)mrow*Hn + col + 8]     = make_float2(cc[4], cc[5]);
        *(float2*)&g_h[(size_t)(mrow+8)*Hn + col + 8] = make_float2(cc[6], cc[7]);
    }
}

// ---------------- routing: column exp-sum (softmax over batch axis) ----------------
__global__ __launch_bounds__(256) void k_r1() {
    __shared__ float red[256];
    int ks = blockIdx.x, tid = threadIdx.x;
    float sm = 0.f;
    for (int b = tid; b < Bn; b += 256) sm += __expf(g_cw[ks*Bn + b]);
    red[tid] = sm; __syncthreads();
    for (int s = 128; s > 0; s >>= 1) { if (tid < s) red[tid] += red[tid+s]; __syncthreads(); }
    if (tid == 0) g_colsum[ks] = red[0];
}

// ---------------- routing: per-batch capsule update ----------------
template<bool FINAL>
__global__ __launch_bounds__(128) void k_r2(const float* __restrict__ mask,
                                            float* __restrict__ ue_out) {
    __shared__ float hsm[Sn*Hn];
    __shared__ float swsm[KSn];
    __shared__ float capsm[128];
    __shared__ float cossm[4], cosrm[4];
    __shared__ int ksel;
    int b = blockIdx.x, tid = threadIdx.x;

    const float4* hp = (const float4*)(g_h + (size_t)b*Sn*Hn);
    float4* h4 = (float4*)hsm;
    for (int i = tid; i < Sn*Hn/4; i += 128) h4[i] = hp[i];
    for (int t = tid; t < KSn; t += 128) {
        int s = t % Sn;
        float cwv = g_cw[(size_t)t*Bn + b];
        float m = mask[b*Sn + s];
        swsm[t] = (m != 0.f) ? __expf(cwv) / g_colsum[t] : 0.f;
    }
    __syncthreads();

    int k = tid >> 5, c = tid & 31;
    float g = 0.f;
    #pragma unroll
    for (int s = 0; s < Sn; s++) g += swsm[k*Sn + s] * hsm[s*Hn + k*32 + c];

    float n = g*g;
    #pragma unroll
    for (int o = 16; o; o >>= 1) n += __shfl_xor_sync(0xffffffffu, n, o);
    n *= 4.f;
    float sc = n / (1.f + n) / sqrtf(n + 1e-9f);
    float cap = sc * g;

    capsm[tid] = cap;
    if (FINAL) {
        float cz = cap * g_ie4[b*32 + c];
        float cr = cap * g_ie4r[b*32 + c];
        #pragma unroll
        for (int o = 16; o; o >>= 1) {
            cz += __shfl_xor_sync(0xffffffffu, cz, o);
            cr += __shfl_xor_sync(0xffffffffu, cr, o);
        }
        if (c == 0) { cossm[k] = cz; cosrm[k] = cr; }
    }
    __syncthreads();

    if (!FINAL) {
        // delta[k,s] = 4 * sum_c cap[k,c]*h[s,k*32+c]
        #pragma unroll
        for (int pass = 0; pass < 2; pass++) {
            int s = c + pass*32;
            if (s < Sn) {
                float d = 0.f;
                #pragma unroll
                for (int i = 0; i < 32; i++) {
                    int cc2 = (c + i) & 31;
                    d += capsm[k*32 + cc2] * hsm[s*Hn + k*32 + cc2];
                }
                g_cw[(size_t)(k*Sn + s)*Bn + b] += 4.f * d;
            }
        }
    } else {
        if (tid == 0) {
            float bst = -3.4e38f; int kb = 0;
            #pragma unroll
            for (int kk = 0; kk < 4; kk++) if (cossm[kk] > bst) { bst = cossm[kk]; kb = kk; }
            ksel = kb;
            g_tgt[b] = cosrm[kb];         // target score uses RAW emb row
        }
        __syncthreads();
        for (int t = tid; t < 512; t += 128) {
            int kk = t >> 7, j = t & 127;
            ue_out[b*512 + t] = capsm[kk*32 + (j >> 2)];
        }
        if (tid < 64) {
            const float L2E = 1.4426950408889634f;
            float x = capsm[ksel*32 + ((2*tid) >> 2)]     * L2E;
            float y = capsm[ksel*32 + ((2*tid + 1) >> 2)] * L2E;
            g_bestbf_u[b*64 + tid] = pack_bf16(x, y);
        }
    }
}

// ---------------- scores GEMM via HMMA + fused exp2 row-sum ----------------
// grid (NCHUNK, 2): each CTA owns M=512 rows (four A tiles) x one v-chunk.
// 8 warps x 64 M rows (4 m16 frags); B double-buffered. 192KB smem, 1 CTA/SM.
#define KD_SMEM (6*32768)
__device__ __forceinline__ void load_tile(unsigned sbase, const char* gsrc, int tid) {
    int row = tid >> 1;
    int c0  = (tid & 1) * 8;
    const char* g = gsrc + row * 256;
    unsigned s = sbase + row * 256;
    #pragma unroll
    for (int j = 0; j < 8; j++) {
        int c16 = c0 + j;
        cp16(s + ((c16 ^ (row & 7)) << 4), g + c16 * 16);
    }
}

__global__ __launch_bounds__(256, 1) void k_d_mma() {
    extern __shared__ char dsm[];
    int tid = threadIdx.x, wid = tid >> 5, lane = tid & 31;
    int mhalf = blockIdx.y, c = blockIdx.x;
    int t0  = c*10 + min(c, 42);          // 42 chunks of 11 tiles, 32 of 10
    int cnt = 10 + (c < 42 ? 1 : 0);

    unsigned aS = smem_u32(dsm);          // 4 A tiles: 128KB
    unsigned bS[2] = { aS + 131072u, aS + 163840u };

    const char* aG = (const char*)g_bestbf_u + (size_t)mhalf * 131072;
    #pragma unroll
    for (int f = 0; f < 4; f++)
        load_tile(aS + f*32768u, aG + f*32768, tid);
    load_tile(bS[0], (const char*)g_embbf_u + (size_t)t0 * 32768, tid);
    CP_COMMIT();

    int rloc = (lane & 7) + ((lane >> 3) & 1) * 8;
    int kcA = lane >> 4;
    int rBl = ((lane >> 4) & 1) * 8 + (lane & 7);
    int khB = (lane >> 3) & 1;

    unsigned a[4][8][4];                  // 4 m16 frags x 8 k-steps
    float acc[8];
    #pragma unroll
    for (int j = 0; j < 8; j++) acc[j] = 0.f;

    #pragma unroll 1
    for (int t = 0; t < cnt; t++) {
        if (t + 1 < cnt) {
            load_tile(bS[(t + 1) & 1], (const char*)g_embbf_u + (size_t)(t0 + t + 1) * 32768, tid);
            CP_COMMIT();
            CP_WAIT(1);
        } else {
            CP_WAIT(0);
        }
        __syncthreads();

        if (t == 0) {
            #pragma unroll
            for (int f = 0; f < 4; f++) {
                int r = wid*64 + f*16 + rloc;
                #pragma unroll
                for (int k = 0; k < 8; k++) {
                    int c16 = k*2 + kcA;
                    ldsm_x4(a[f][k][0], a[f][k][1], a[f][k][2], a[f][k][3],
                            aS + r*256 + ((c16 ^ (r & 7)) << 4));
                }
            }
        }

        unsigned bb = bS[t & 1];
        #pragma unroll 1
        for (int np = 0; np < 8; np++) {
            int rB = np*16 + rBl;
            unsigned baddr0 = bb + rB*256;
            float cc[32];
            #pragma unroll
            for (int j = 0; j < 32; j++) cc[j] = 0.f;
            #pragma unroll
            for (int k = 0; k < 8; k++) {
                int c16 = k*2 + khB;
                unsigned b0, b1, b2, b3;
                ldsm_x4(b0, b1, b2, b3, baddr0 + ((c16 ^ (rB & 7)) << 4));
                #pragma unroll
                for (int f = 0; f < 4; f++) {
                    mma16816(cc + f*8,     a[f][k], b0, b1);
                    mma16816(cc + f*8 + 4, a[f][k], b2, b3);
                }
            }
            #pragma unroll
            for (int f = 0; f < 4; f++) {
                acc[f*2]   += ex2f(cc[f*8+0]) + ex2f(cc[f*8+1]) + ex2f(cc[f*8+4]) + ex2f(cc[f*8+5]);
                acc[f*2+1] += ex2f(cc[f*8+2]) + ex2f(cc[f*8+3]) + ex2f(cc[f*8+6]) + ex2f(cc[f*8+7]);
            }
        }
        __syncthreads();
    }

    #pragma unroll
    for (int j = 0; j < 8; j++) {
        acc[j] += __shfl_xor_sync(0xffffffffu, acc[j], 1);
        acc[j] += __shfl_xor_sync(0xffffffffu, acc[j], 2);
    }
    if ((lane & 3) == 0) {
        int r0 = mhalf*512 + wid*64 + (lane >> 2);
        #pragma unroll
        for (int f = 0; f < 4; f++) {
            g_partial[c*Bn + r0 + f*16]     = acc[f*2];
            g_partial[c*Bn + r0 + f*16 + 8] = acc[f*2+1];
        }
    }
}

// ---------------- final loss reduction ----------------
__global__ __launch_bounds__(1024) void k_e(float* __restrict__ loss_out) {
    __shared__ float red[1024];
    int tid = threadIdx.x;
    float acc = -96.0f;   // remove exp(0)=1 from the 96 zero-padded v columns
    for (int c = 0; c < NCHUNK; c++) acc += g_partial[c*Bn + tid];
    red[tid] = g_tgt[tid] - logf(acc);
    __syncthreads();
    for (int s = 512; s > 0; s >>= 1) { if (tid < s) red[tid] += red[tid+s]; __syncthreads(); }
    if (tid == 0) loss_out[0] = -red[0] / (float)Bn;
}

// ---------------- host launcher ----------------
extern "C" void kernel_launch(void* const* d_in, const int* in_sizes, int n_in,
                              void* d_out, int out_size) {
    const int*   item_seq = (const int*)  d_in[0];
    const float* mask     = (const float*)d_in[1];
    const int*   item     = (const int*)  d_in[2];
    const float* emb      = (const float*)d_in[3];
    const float* W        = (const float*)d_in[4];
    const float* cw0      = (const float*)d_in[5];
    float* out = (float*)d_out;

    float *ue_ptr, *loss_ptr;
    if (out_size >= BKH + 1)      { ue_ptr = out;          loss_ptr = out + BKH; }
    else if (out_size == BKH)     { ue_ptr = out;          loss_ptr = g_loss_scratch; }
    else                          { ue_ptr = g_ue_scratch; loss_ptr = out + (out_size > 0 ? out_size - 1 : 0); }

    cudaFuncSetAttribute(k_h_mma, cudaFuncAttributeMaxDynamicSharedMemorySize, KH_SMEM);
    cudaFuncSetAttribute(k_d_mma, cudaFuncAttributeMaxDynamicSharedMemorySize, KD_SMEM);

    // side stream: routing prologue (init_cw -> r1_0 -> ie4) + emb bf16 conversion,
    // all concurrent with the conv_w -> k_h chain on the main stream.
    cudaStream_t s2; cudaEvent_t evF, evR, evE;
    cudaStreamCreateWithFlags(&s2, cudaStreamNonBlocking);
    cudaEventCreateWithFlags(&evF, cudaEventDisableTiming);
    cudaEventCreateWithFlags(&evR, cudaEventDisableTiming);
    cudaEventCreateWithFlags(&evE, cudaEventDisableTiming);
    cudaEventRecord(evF, 0);
    cudaStreamWaitEvent(s2, evF, 0);
    k_init_cw<<<KSn, 256, 0, s2>>>(cw0);
    k_r1<<<KSn, 256, 0, s2>>>();                 // colsum for routing iter 0
    k_ie4<<<Bn, 32, 0, s2>>>(item, emb);
    cudaEventRecord(evR, s2);
    k_conv_emb<<<(VP*64)/256, 256, 0, s2>>>(emb);
    cudaEventRecord(evE, s2);

    // main chain
    k_conv_w<<<(Hn*64)/256, 256>>>(W);
    k_h_mma<<<(Bn*Sn)/128, 256, KH_SMEM>>>(item_seq, emb);

    cudaStreamWaitEvent(0, evR, 0);              // routing prologue ready
    k_r2<false><<<Bn, 128>>>(mask, ue_ptr);
    k_r1<<<KSn, 256>>>();
    k_r2<false><<<Bn, 128>>>(mask, ue_ptr);
    k_r1<<<KSn, 256>>>();
    k_r2<true ><<<Bn, 128>>>(mask, ue_ptr);

    cudaStreamWaitEvent(0, evE, 0);              // emb bf16 ready
    k_d_mma<<<dim3(NCHUNK, 2), 256, KD_SMEM>>>();
    k_e<<<1, 1024>>>(loss_ptr);
}